// round 3
// baseline (speedup 1.0000x reference)
#include <cuda_runtime.h>
#include <math.h>

// ---------------- problem constants ----------------
#define BATCH   2
#define SEQLEN  1024
#define DMODEL  1024
#define DINNER  2048
#define DSTATE  16
#define DTRANK  64
#define MTOT    (BATCH*SEQLEN)        // 2048 rows (b*L + l)
#define NXPROJ  (DTRANK + 2*DSTATE)   // 96

// ---------------- scratch (device globals; no allocation) ----------------
__device__ float g_xz  [MTOT * 2*DINNER];  // [m, 4096]  x | z
__device__ float g_u   [MTOT * DINNER];    // [m, d]     conv+silu output
__device__ float g_uT  [BATCH * DINNER * SEQLEN]; // [(b*2048+d), l]
__device__ float g_xdbl[MTOT * NXPROJ];    // [m, 96]    dt_low | B | C
__device__ float g_dT  [BATCH * DINNER * SEQLEN]; // delta transposed [(b*2048+d), l]
__device__ float g_y   [MTOT * DINNER];    // scan output [m, d]
__device__ float g_y2  [MTOT * DINNER];    // gated

__device__ __forceinline__ float siluf(float x) { return x / (1.f + __expf(-x)); }

// ---------------- 128x128x16 fp32 SGEMM, C[m,n] = sum_k A[m,K]*B[n,K] (NT) ----------------
__global__ __launch_bounds__(256, 2) void sgemm_nt(
    const float* __restrict__ A, const float* __restrict__ B,
    float* __restrict__ C, int M, int N, int K)
{
    __shared__ float As[16][128];
    __shared__ float Bs[16][128];
    const int tid = threadIdx.x;
    const int m0 = blockIdx.y * 128, n0 = blockIdx.x * 128;
    const int lrow = tid >> 2;              // 0..63
    const int lcol = (tid & 3) << 2;        // 0,4,8,12
    const int tx = tid & 15, ty = tid >> 4; // 16x16 compute layout

    float acc[8][8];
#pragma unroll
    for (int i = 0; i < 8; i++)
#pragma unroll
        for (int j = 0; j < 8; j++) acc[i][j] = 0.f;

    const float* Ap = A + (size_t)(m0 + lrow) * K + lcol;
    const float* Bp = B + (size_t)(n0 + lrow) * K + lcol;

    for (int k0 = 0; k0 < K; k0 += 16) {
        float4 a0 = *(const float4*)(Ap + k0);
        float4 a1 = *(const float4*)(Ap + (size_t)64 * K + k0);
        float4 b0 = *(const float4*)(Bp + k0);
        float4 b1 = *(const float4*)(Bp + (size_t)64 * K + k0);
        As[lcol + 0][lrow]      = a0.x; As[lcol + 1][lrow]      = a0.y;
        As[lcol + 2][lrow]      = a0.z; As[lcol + 3][lrow]      = a0.w;
        As[lcol + 0][lrow + 64] = a1.x; As[lcol + 1][lrow + 64] = a1.y;
        As[lcol + 2][lrow + 64] = a1.z; As[lcol + 3][lrow + 64] = a1.w;
        Bs[lcol + 0][lrow]      = b0.x; Bs[lcol + 1][lrow]      = b0.y;
        Bs[lcol + 2][lrow]      = b0.z; Bs[lcol + 3][lrow]      = b0.w;
        Bs[lcol + 0][lrow + 64] = b1.x; Bs[lcol + 1][lrow + 64] = b1.y;
        Bs[lcol + 2][lrow + 64] = b1.z; Bs[lcol + 3][lrow + 64] = b1.w;
        __syncthreads();
#pragma unroll
        for (int k = 0; k < 16; k++) {
            float ra[8], rb[8];
            *(float4*)(ra)     = *(const float4*)(&As[k][ty * 8]);
            *(float4*)(ra + 4) = *(const float4*)(&As[k][ty * 8 + 4]);
            *(float4*)(rb)     = *(const float4*)(&Bs[k][tx * 8]);
            *(float4*)(rb + 4) = *(const float4*)(&Bs[k][tx * 8 + 4]);
#pragma unroll
            for (int i = 0; i < 8; i++)
#pragma unroll
                for (int j = 0; j < 8; j++)
                    acc[i][j] = fmaf(ra[i], rb[j], acc[i][j]);
        }
        __syncthreads();
    }
#pragma unroll
    for (int i = 0; i < 8; i++) {
        float* Cp = C + (size_t)(m0 + ty * 8 + i) * N + n0 + tx * 8;
        float4 v0 = make_float4(acc[i][0], acc[i][1], acc[i][2], acc[i][3]);
        float4 v1 = make_float4(acc[i][4], acc[i][5], acc[i][6], acc[i][7]);
        *(float4*)Cp       = v0;
        *(float4*)(Cp + 4) = v1;
    }
}

// ---------------- causal depthwise conv (K=4) + SiLU; write u and u^T ----------------
// tile: 32 l x 32 d
__global__ void conv_silu_kernel(const float* __restrict__ cw, const float* __restrict__ cb)
{
    __shared__ float Ts[32][33];
    const int tid = threadIdx.x;                 // 256
    const int m0 = blockIdx.x * 32, d0 = blockIdx.y * 32;
    const int b = m0 >> 10;                      // m0 / 1024
    const int l0 = m0 & 1023;
    const int di = tid & 31, lg = tid >> 5;      // lg 0..7
    const int d = d0 + di;
    const float w0 = cw[d * 4 + 0], w1 = cw[d * 4 + 1];
    const float w2 = cw[d * 4 + 2], w3 = cw[d * 4 + 3];
    const float bias = cb[d];
#pragma unroll
    for (int j = 0; j < 4; j++) {
        const int li = lg * 4 + j;
        const int l = l0 + li;
        const int m = m0 + li;
        float s = bias;
        const float* xcol = g_xz + (size_t)m * (2 * DINNER) + d;
        if (l >= 3) s = fmaf(xcol[-3 * 2 * DINNER], w0, s);
        if (l >= 2) s = fmaf(xcol[-2 * 2 * DINNER], w1, s);
        if (l >= 1) s = fmaf(xcol[-1 * 2 * DINNER], w2, s);
        s = fmaf(xcol[0], w3, s);
        const float uv = siluf(s);
        g_u[(size_t)m * DINNER + d] = uv;
        Ts[li][di] = uv;
    }
    __syncthreads();
    const int li2 = tid & 31, dg = tid >> 5;
#pragma unroll
    for (int j = 0; j < 4; j++) {
        const int di2 = dg * 4 + j;
        g_uT[(size_t)(b * DINNER + d0 + di2) * SEQLEN + l0 + li2] = Ts[li2][di2];
    }
}

// ---------------- x_dbl = u @ x_proj_w^T  (M=2048, N=96, K=2048) ----------------
__global__ void gemm_xdbl_kernel(const float* __restrict__ W)
{
    __shared__ float Us[32][33];
    __shared__ float Ws[96][33];
    const int tid = threadIdx.x;            // 256
    const int m0 = blockIdx.x * 32;
    const int tn = tid & 15, tm = tid >> 4; // tn -> 6 n's, tm -> 2 m's
    float acc[2][6];
#pragma unroll
    for (int i = 0; i < 2; i++)
#pragma unroll
        for (int j = 0; j < 6; j++) acc[i][j] = 0.f;

    const int ulr = tid >> 3, ulc = (tid & 7) << 2;     // U: 1 float4/thread
    for (int k0 = 0; k0 < DINNER; k0 += 32) {
        float4 uv = *(const float4*)(g_u + (size_t)(m0 + ulr) * DINNER + k0 + ulc);
        Us[ulr][ulc + 0] = uv.x; Us[ulr][ulc + 1] = uv.y;
        Us[ulr][ulc + 2] = uv.z; Us[ulr][ulc + 3] = uv.w;
#pragma unroll
        for (int i = 0; i < 3; i++) {
            int idx = tid + i * 256;        // 768 float4 for 96x32
            int wr = idx >> 3, wc = (idx & 7) << 2;
            float4 wv = *(const float4*)(W + (size_t)wr * DINNER + k0 + wc);
            Ws[wr][wc + 0] = wv.x; Ws[wr][wc + 1] = wv.y;
            Ws[wr][wc + 2] = wv.z; Ws[wr][wc + 3] = wv.w;
        }
        __syncthreads();
#pragma unroll 8
        for (int k = 0; k < 32; k++) {
            float u0 = Us[tm * 2 + 0][k];
            float u1 = Us[tm * 2 + 1][k];
#pragma unroll
            for (int j = 0; j < 6; j++) {
                float w = Ws[tn * 6 + j][k];
                acc[0][j] = fmaf(u0, w, acc[0][j]);
                acc[1][j] = fmaf(u1, w, acc[1][j]);
            }
        }
        __syncthreads();
    }
#pragma unroll
    for (int i = 0; i < 2; i++)
#pragma unroll
        for (int j = 0; j < 6; j++)
            g_xdbl[(size_t)(m0 + tm * 2 + i) * NXPROJ + tn * 6 + j] = acc[i][j];
}

// ---------------- delta (transposed): softplus(dt_low @ dt_w^T + 2*dt_b) ----------------
// tile: 32 m x 32 d; K=64
__global__ void dt_delta_kernel(const float* __restrict__ Wd, const float* __restrict__ bd)
{
    __shared__ float Xs[32][65];
    __shared__ float Ws[32][65];
    const int tid = threadIdx.x;                     // 256
    const int m0 = blockIdx.x * 32, d0 = blockIdx.y * 32;
    const int lr = tid >> 4;                         // 0..15 (rows lr, lr+16)
    const int lc = (tid & 15) << 2;                  // 0..60
#pragma unroll
    for (int i = 0; i < 2; i++) {
        int r = lr + i * 16;
        float4 xv = *(const float4*)(g_xdbl + (size_t)(m0 + r) * NXPROJ + lc);
        Xs[r][lc + 0] = xv.x; Xs[r][lc + 1] = xv.y; Xs[r][lc + 2] = xv.z; Xs[r][lc + 3] = xv.w;
        float4 wv = *(const float4*)(Wd + (size_t)(d0 + r) * DTRANK + lc);
        Ws[r][lc + 0] = wv.x; Ws[r][lc + 1] = wv.y; Ws[r][lc + 2] = wv.z; Ws[r][lc + 3] = wv.w;
    }
    __syncthreads();
    const int li = tid & 31, dg = tid >> 5;          // li: l within tile, dg: 4 d's
    float acc[4] = {0.f, 0.f, 0.f, 0.f};
#pragma unroll 8
    for (int k = 0; k < 64; k++) {
        float xv = Xs[li][k];
#pragma unroll
        for (int j = 0; j < 4; j++)
            acc[j] = fmaf(xv, Ws[dg * 4 + j][k], acc[j]);
    }
    const int b = m0 >> 10;
    const int l = (m0 & 1023) + li;
#pragma unroll
    for (int j = 0; j < 4; j++) {
        const int d = d0 + dg * 4 + j;
        float x = acc[j] + 2.f * bd[d];
        float sp = (x > 20.f) ? x : log1pf(__expf(x));
        g_dT[(size_t)(b * DINNER + d) * SEQLEN + l] = sp;
    }
}

// ---------------- selective scan: lane-per-state, 2 channels per warp ----------------
__global__ void scan_kernel(const float* __restrict__ A_log)
{
    const int warp = (blockIdx.x * blockDim.x + threadIdx.x) >> 5; // 0..2047
    const int lane = threadIdx.x & 31;
    const int b = warp >> 10;
    const int dp = warp & 1023;
    const int half = lane >> 4, n = lane & 15;
    const int d = dp * 2 + half;
    const int ch = b * DINNER + d;
    const float a = -__expf(A_log[d * DSTATE + n]);
    const float* dch = g_dT + (size_t)ch * SEQLEN;
    const float* uch = g_uT + (size_t)ch * SEQLEN;
    const int mbase = b * SEQLEN;
    float s = 0.f;
#pragma unroll 4
    for (int l = 0; l < SEQLEN; l++) {
        const int m = mbase + l;
        const float dl = dch[l];
        const float uu = uch[l];
        const float Bn = g_xdbl[(size_t)m * NXPROJ + DTRANK + n];
        const float Cn = g_xdbl[(size_t)m * NXPROJ + DTRANK + DSTATE + n];
        s = fmaf(__expf(dl * a), s, dl * uu * Bn);
        float c = s * Cn;
        c += __shfl_xor_sync(0xffffffffu, c, 8);
        c += __shfl_xor_sync(0xffffffffu, c, 4);
        c += __shfl_xor_sync(0xffffffffu, c, 2);
        c += __shfl_xor_sync(0xffffffffu, c, 1);
        if (n == 0) g_y[(size_t)m * DINNER + d] = c;
    }
}

// ---------------- gating: y2 = (y + u*D) * silu(z) ----------------
__global__ void gate_kernel(const float* __restrict__ Dv)
{
    const int idx = blockIdx.x * blockDim.x + threadIdx.x;  // < 2048*2048
    const int m = idx >> 11, d = idx & 2047;
    const float z = g_xz[(size_t)m * (2 * DINNER) + DINNER + d];
    g_y2[idx] = (g_y[idx] + g_u[idx] * Dv[d]) * siluf(z);
}

// ---------------- launcher ----------------
extern "C" void kernel_launch(void* const* d_in, const int* in_sizes, int n_in,
                              void* d_out, int out_size)
{
    const float* hs      = (const float*)d_in[0];  // [2,1024,1024]
    const float* inW     = (const float*)d_in[1];  // [4096,1024]
    const float* convW   = (const float*)d_in[2];  // [2048,1,4]
    const float* convB   = (const float*)d_in[3];  // [2048]
    const float* xprojW  = (const float*)d_in[4];  // [96,2048]
    const float* dtW     = (const float*)d_in[5];  // [2048,64]
    const float* dtB     = (const float*)d_in[6];  // [2048]
    const float* A_log   = (const float*)d_in[7];  // [2048,16]
    const float* Dv      = (const float*)d_in[8];  // [2048]
    const float* outW    = (const float*)d_in[9];  // [1024,2048]
    float* out = (float*)d_out;

    float *p_xz, *p_y2;
    cudaGetSymbolAddress((void**)&p_xz, g_xz);
    cudaGetSymbolAddress((void**)&p_y2, g_y2);

    // 1) xz = hs @ in_proj_w^T : [2048,1024] x [4096,1024]^T
    sgemm_nt<<<dim3(2 * DINNER / 128, MTOT / 128), 256>>>(hs, inW, p_xz, MTOT, 2 * DINNER, DMODEL);

    // 2) causal depthwise conv + SiLU -> u, uT
    conv_silu_kernel<<<dim3(MTOT / 32, DINNER / 32), 256>>>(convW, convB);

    // 3) x_dbl = u @ x_proj_w^T
    gemm_xdbl_kernel<<<MTOT / 32, 256>>>(xprojW);

    // 4) delta (transposed layout)
    dt_delta_kernel<<<dim3(MTOT / 32, DINNER / 32), 256>>>(dtW, dtB);

    // 5) selective scan
    scan_kernel<<<(BATCH * DINNER / 2) / 8, 256>>>(A_log);   // 2048 warps

    // 6) gating
    gate_kernel<<<(MTOT * DINNER) / 256, 256>>>(Dv);

    // 7) out = y2 @ out_proj_w^T
    sgemm_nt<<<dim3(DMODEL / 128, MTOT / 128), 256>>>(p_y2, outW, out, MTOT, DMODEL, DINNER);
}

// round 5
// speedup vs baseline: 1.5315x; 1.5315x over previous
#include <cuda_runtime.h>
#include <cuda_bf16.h>
#include <math.h>
#include <stdint.h>

// ---------------- problem constants ----------------
#define BATCH   2
#define SEQLEN  1024
#define DMODEL  1024
#define DINNER  2048
#define DSTATE  16
#define DTRANK  64
#define MTOT    (BATCH*SEQLEN)        // 2048 rows (b*L + l)
#define NXPROJ  (DTRANK + 2*DSTATE)   // 96

// ---------------- scratch (device globals; no allocation) ----------------
__device__ float g_xz  [MTOT * 2*DINNER];  // [m, 4096]  x | z
__device__ float g_u   [MTOT * DINNER];    // [m, d]     conv+silu output
__device__ float g_uT  [BATCH * DINNER * SEQLEN]; // [(b*2048+d), l]
__device__ float g_xdbl[MTOT * NXPROJ];    // [m, 96]    dt_low | B | C
__device__ float g_dT  [BATCH * DINNER * SEQLEN]; // delta transposed
__device__ float g_y   [MTOT * DINNER];    // scan output [m, d]
__device__ float g_y2  [MTOT * DINNER];    // gated

// split-bf16 operands (row-major hi / lo)
__device__ __nv_bfloat16 g_hsH  [MTOT * DMODEL],      g_hsL  [MTOT * DMODEL];
__device__ __nv_bfloat16 g_inWH [2*DINNER * DMODEL],  g_inWL [2*DINNER * DMODEL];
__device__ __nv_bfloat16 g_y2H  [MTOT * DINNER],      g_y2L  [MTOT * DINNER];
__device__ __nv_bfloat16 g_outWH[DMODEL * DINNER],    g_outWL[DMODEL * DINNER];

__device__ __forceinline__ float siluf(float x) { return x / (1.f + __expf(-x)); }

// ================= mma helpers (sm_80-compatible PTX) =================
#define MMA_BF16(d, a, b)                                                     \
    asm volatile("mma.sync.aligned.m16n8k16.row.col.f32.bf16.bf16.f32 "       \
        "{%0,%1,%2,%3}, {%4,%5,%6,%7}, {%8,%9}, {%0,%1,%2,%3};"               \
        : "+f"((d)[0]), "+f"((d)[1]), "+f"((d)[2]), "+f"((d)[3])              \
        : "r"((a)[0]), "r"((a)[1]), "r"((a)[2]), "r"((a)[3]),                 \
          "r"((b)[0]), "r"((b)[1]))

#define LDSM4(r, addr)                                                        \
    asm volatile("ldmatrix.sync.aligned.m8n8.x4.shared.b16 {%0,%1,%2,%3}, [%4];" \
        : "=r"((r)[0]), "=r"((r)[1]), "=r"((r)[2]), "=r"((r)[3]) : "r"(addr))

#define CP_ASYNC16(s, g)                                                      \
    asm volatile("cp.async.cg.shared.global [%0], [%1], 16;" :: "r"(s), "l"(g))

// ---------------- split fp32 -> (hi,lo) bf16 row-major ----------------
__global__ void split_kernel(const float* __restrict__ src,
                             __nv_bfloat16* __restrict__ hi,
                             __nv_bfloat16* __restrict__ lo)
{
    const int idx = blockIdx.x * blockDim.x + threadIdx.x;   // elems/4
    float4 v = ((const float4*)src)[idx];
    float f[4] = {v.x, v.y, v.z, v.w};
    union { __nv_bfloat16 h[4]; uint2 u; } H, L;
#pragma unroll
    for (int i = 0; i < 4; i++) {
        __nv_bfloat16 hh = __float2bfloat16(f[i]);
        H.h[i] = hh;
        L.h[i] = __float2bfloat16(f[i] - __bfloat162float(hh));
    }
    ((uint2*)hi)[idx] = H.u;
    ((uint2*)lo)[idx] = L.u;
}

// ---------------- 3-term split-bf16 MMA GEMM: C[m,n] = A[m,:]·B[n,:] (NT) ----------------
// 128x128 CTA tile, BK=32, 8 warps (warp tile 32x64), cp.async double buffer.
#define SASTRIDE 40                       // bf16 elems per smem row (80B, 16B-aligned)
#define MATB     (128 * SASTRIDE * 2)     // bytes per matrix tile (10240)
#define BUFB     (4 * MATB)               // bytes per buffer (40960)
#define GEMM_SMEM (2 * BUFB)              // 81920

__global__ __launch_bounds__(256, 1) void mma_gemm(
    const __nv_bfloat16* __restrict__ Ah, const __nv_bfloat16* __restrict__ Al,
    const __nv_bfloat16* __restrict__ Bh, const __nv_bfloat16* __restrict__ Bl,
    float* __restrict__ C, int N, int K)
{
    extern __shared__ __align__(128) char smem[];
    const uint32_t sb = (uint32_t)__cvta_generic_to_shared(smem);
    const int tid = threadIdx.x, lane = tid & 31, wid = tid >> 5;
    const int wm = wid >> 1, wn = wid & 1;            // 4x2 warps
    const int m0 = blockIdx.y * 128, n0 = blockIdx.x * 128;
    const int KT = K >> 5;

    const __nv_bfloat16* gp0 = Ah + (size_t)m0 * K;
    const __nv_bfloat16* gp1 = Al + (size_t)m0 * K;
    const __nv_bfloat16* gp2 = Bh + (size_t)n0 * K;
    const __nv_bfloat16* gp3 = Bl + (size_t)n0 * K;

    const int lrow = tid >> 2;            // c = tid: row c>>2
    const int lcol = (tid & 3) * 8;
    const int lrow2 = (tid + 256) >> 2;
    const int lcol2 = ((tid + 256) & 3) * 8;

    float acc[2][8][4];
#pragma unroll
    for (int i = 0; i < 2; i++)
#pragma unroll
        for (int j = 0; j < 8; j++)
#pragma unroll
            for (int q = 0; q < 4; q++) acc[i][j][q] = 0.f;

#define LOAD_TILE(KT_IDX, BUF) do {                                           \
    const int _kO = (KT_IDX) * 32;                                            \
    const uint32_t _sB = sb + (BUF) * BUFB;                                   \
    CP_ASYNC16(_sB + 0*MATB + (lrow  * SASTRIDE + lcol ) * 2, gp0 + (size_t)lrow  * K + _kO + lcol ); \
    CP_ASYNC16(_sB + 0*MATB + (lrow2 * SASTRIDE + lcol2) * 2, gp0 + (size_t)lrow2 * K + _kO + lcol2); \
    CP_ASYNC16(_sB + 1*MATB + (lrow  * SASTRIDE + lcol ) * 2, gp1 + (size_t)lrow  * K + _kO + lcol ); \
    CP_ASYNC16(_sB + 1*MATB + (lrow2 * SASTRIDE + lcol2) * 2, gp1 + (size_t)lrow2 * K + _kO + lcol2); \
    CP_ASYNC16(_sB + 2*MATB + (lrow  * SASTRIDE + lcol ) * 2, gp2 + (size_t)lrow  * K + _kO + lcol ); \
    CP_ASYNC16(_sB + 2*MATB + (lrow2 * SASTRIDE + lcol2) * 2, gp2 + (size_t)lrow2 * K + _kO + lcol2); \
    CP_ASYNC16(_sB + 3*MATB + (lrow  * SASTRIDE + lcol ) * 2, gp3 + (size_t)lrow  * K + _kO + lcol ); \
    CP_ASYNC16(_sB + 3*MATB + (lrow2 * SASTRIDE + lcol2) * 2, gp3 + (size_t)lrow2 * K + _kO + lcol2); \
    asm volatile("cp.async.commit_group;" ::: "memory");                      \
} while (0)

    LOAD_TILE(0, 0);

    const int arow = wm * 32 + (lane & 15);
    const int acolb = (lane >> 4) * 8;
    const int brow = wn * 64 + (lane & 7) + ((lane >> 4) << 3);
    const int bcolb = ((lane >> 3) & 1) * 8;

    for (int kt = 0; kt < KT; kt++) {
        const int buf = kt & 1;
        if (kt + 1 < KT) {
            LOAD_TILE(kt + 1, (kt + 1) & 1);
            asm volatile("cp.async.wait_group 1;" ::: "memory");
        } else {
            asm volatile("cp.async.wait_group 0;" ::: "memory");
        }
        __syncthreads();

        const uint32_t base = sb + buf * BUFB;
#pragma unroll
        for (int ks = 0; ks < 2; ks++) {
            uint32_t aH[2][4], aL[2][4], bH[8][2], bL[8][2];
            const int acol = ks * 16 + acolb;
            LDSM4(aH[0], base + ((arow)      * SASTRIDE + acol) * 2);
            LDSM4(aH[1], base + ((arow + 16) * SASTRIDE + acol) * 2);
            LDSM4(aL[0], base + MATB + ((arow)      * SASTRIDE + acol) * 2);
            LDSM4(aL[1], base + MATB + ((arow + 16) * SASTRIDE + acol) * 2);
            const int bcol = ks * 16 + bcolb;
#pragma unroll
            for (int p = 0; p < 4; p++) {
                uint32_t r[4];
                LDSM4(r, base + 2 * MATB + ((brow + p * 16) * SASTRIDE + bcol) * 2);
                bH[2 * p][0] = r[0]; bH[2 * p][1] = r[1];
                bH[2 * p + 1][0] = r[2]; bH[2 * p + 1][1] = r[3];
                LDSM4(r, base + 3 * MATB + ((brow + p * 16) * SASTRIDE + bcol) * 2);
                bL[2 * p][0] = r[0]; bL[2 * p][1] = r[1];
                bL[2 * p + 1][0] = r[2]; bL[2 * p + 1][1] = r[3];
            }
#pragma unroll
            for (int mt = 0; mt < 2; mt++)
#pragma unroll
                for (int nt = 0; nt < 8; nt++) {
                    MMA_BF16(acc[mt][nt], aH[mt], bH[nt]);
                    MMA_BF16(acc[mt][nt], aL[mt], bH[nt]);
                    MMA_BF16(acc[mt][nt], aH[mt], bL[nt]);
                }
        }
        __syncthreads();
    }

    // epilogue
#pragma unroll
    for (int mt = 0; mt < 2; mt++) {
        const int row = m0 + wm * 32 + mt * 16 + (lane >> 2);
#pragma unroll
        for (int nt = 0; nt < 8; nt++) {
            const int col = n0 + wn * 64 + nt * 8 + (lane & 3) * 2;
            *(float2*)&C[(size_t)row * N + col] =
                make_float2(acc[mt][nt][0], acc[mt][nt][1]);
            *(float2*)&C[(size_t)(row + 8) * N + col] =
                make_float2(acc[mt][nt][2], acc[mt][nt][3]);
        }
    }
#undef LOAD_TILE
}

// ---------------- causal depthwise conv (K=4) + SiLU; write u and u^T ----------------
__global__ void conv_silu_kernel(const float* __restrict__ cw, const float* __restrict__ cb)
{
    __shared__ float Ts[32][33];
    const int tid = threadIdx.x;                 // 256
    const int m0 = blockIdx.x * 32, d0 = blockIdx.y * 32;
    const int b = m0 >> 10;
    const int l0 = m0 & 1023;
    const int di = tid & 31, lg = tid >> 5;
    const int d = d0 + di;
    const float w0 = cw[d * 4 + 0], w1 = cw[d * 4 + 1];
    const float w2 = cw[d * 4 + 2], w3 = cw[d * 4 + 3];
    const float bias = cb[d];
#pragma unroll
    for (int j = 0; j < 4; j++) {
        const int li = lg * 4 + j;
        const int l = l0 + li;
        const int m = m0 + li;
        float s = bias;
        const float* xcol = g_xz + (size_t)m * (2 * DINNER) + d;
        if (l >= 3) s = fmaf(xcol[-3 * 2 * DINNER], w0, s);
        if (l >= 2) s = fmaf(xcol[-2 * 2 * DINNER], w1, s);
        if (l >= 1) s = fmaf(xcol[-1 * 2 * DINNER], w2, s);
        s = fmaf(xcol[0], w3, s);
        const float uv = siluf(s);
        g_u[(size_t)m * DINNER + d] = uv;
        Ts[li][di] = uv;
    }
    __syncthreads();
    const int li2 = tid & 31, dg = tid >> 5;
#pragma unroll
    for (int j = 0; j < 4; j++) {
        const int di2 = dg * 4 + j;
        g_uT[(size_t)(b * DINNER + d0 + di2) * SEQLEN + l0 + li2] = Ts[li2][di2];
    }
}

// ---------------- x_dbl = u @ x_proj_w^T  (M=2048, N=96, K=2048) ----------------
__global__ void gemm_xdbl_kernel(const float* __restrict__ W)
{
    __shared__ float Us[32][33];
    __shared__ float Ws[96][33];
    const int tid = threadIdx.x;            // 256
    const int m0 = blockIdx.x * 32;
    const int tn = tid & 15, tm = tid >> 4;
    float acc[2][6];
#pragma unroll
    for (int i = 0; i < 2; i++)
#pragma unroll
        for (int j = 0; j < 6; j++) acc[i][j] = 0.f;

    const int ulr = tid >> 3, ulc = (tid & 7) << 2;
    for (int k0 = 0; k0 < DINNER; k0 += 32) {
        float4 uv = *(const float4*)(g_u + (size_t)(m0 + ulr) * DINNER + k0 + ulc);
        Us[ulr][ulc + 0] = uv.x; Us[ulr][ulc + 1] = uv.y;
        Us[ulr][ulc + 2] = uv.z; Us[ulr][ulc + 3] = uv.w;
#pragma unroll
        for (int i = 0; i < 3; i++) {
            int idx = tid + i * 256;
            int wr = idx >> 3, wc = (idx & 7) << 2;
            float4 wv = *(const float4*)(W + (size_t)wr * DINNER + k0 + wc);
            Ws[wr][wc + 0] = wv.x; Ws[wr][wc + 1] = wv.y;
            Ws[wr][wc + 2] = wv.z; Ws[wr][wc + 3] = wv.w;
        }
        __syncthreads();
#pragma unroll 8
        for (int k = 0; k < 32; k++) {
            float u0 = Us[tm * 2 + 0][k];
            float u1 = Us[tm * 2 + 1][k];
#pragma unroll
            for (int j = 0; j < 6; j++) {
                float w = Ws[tn * 6 + j][k];
                acc[0][j] = fmaf(u0, w, acc[0][j]);
                acc[1][j] = fmaf(u1, w, acc[1][j]);
            }
        }
        __syncthreads();
    }
#pragma unroll
    for (int i = 0; i < 2; i++)
#pragma unroll
        for (int j = 0; j < 6; j++)
            g_xdbl[(size_t)(m0 + tm * 2 + i) * NXPROJ + tn * 6 + j] = acc[i][j];
}

// ---------------- delta (transposed): softplus(dt_low @ dt_w^T + 2*dt_b) ----------------
__global__ void dt_delta_kernel(const float* __restrict__ Wd, const float* __restrict__ bd)
{
    __shared__ float Xs[32][65];
    __shared__ float Ws[32][65];
    const int tid = threadIdx.x;                     // 256
    const int m0 = blockIdx.x * 32, d0 = blockIdx.y * 32;
    const int lr = tid >> 4;
    const int lc = (tid & 15) << 2;
#pragma unroll
    for (int i = 0; i < 2; i++) {
        int r = lr + i * 16;
        float4 xv = *(const float4*)(g_xdbl + (size_t)(m0 + r) * NXPROJ + lc);
        Xs[r][lc + 0] = xv.x; Xs[r][lc + 1] = xv.y; Xs[r][lc + 2] = xv.z; Xs[r][lc + 3] = xv.w;
        float4 wv = *(const float4*)(Wd + (size_t)(d0 + r) * DTRANK + lc);
        Ws[r][lc + 0] = wv.x; Ws[r][lc + 1] = wv.y; Ws[r][lc + 2] = wv.z; Ws[r][lc + 3] = wv.w;
    }
    __syncthreads();
    const int li = tid & 31, dg = tid >> 5;
    float acc[4] = {0.f, 0.f, 0.f, 0.f};
#pragma unroll 8
    for (int k = 0; k < 64; k++) {
        float xv = Xs[li][k];
#pragma unroll
        for (int j = 0; j < 4; j++)
            acc[j] = fmaf(xv, Ws[dg * 4 + j][k], acc[j]);
    }
    const int b = m0 >> 10;
    const int l = (m0 & 1023) + li;
#pragma unroll
    for (int j = 0; j < 4; j++) {
        const int d = d0 + dg * 4 + j;
        float x = acc[j] + 2.f * bd[d];
        float sp = (x > 20.f) ? x : log1pf(__expf(x));
        g_dT[(size_t)(b * DINNER + d) * SEQLEN + l] = sp;
    }
}

// ---------------- selective scan: lane-per-state, 2 channels per warp ----------------
__global__ void scan_kernel(const float* __restrict__ A_log)
{
    const int warp = (blockIdx.x * blockDim.x + threadIdx.x) >> 5;
    const int lane = threadIdx.x & 31;
    const int b = warp >> 10;
    const int dp = warp & 1023;
    const int half = lane >> 4, n = lane & 15;
    const int d = dp * 2 + half;
    const int ch = b * DINNER + d;
    const float a = -__expf(A_log[d * DSTATE + n]);
    const float* dch = g_dT + (size_t)ch * SEQLEN;
    const float* uch = g_uT + (size_t)ch * SEQLEN;
    const int mbase = b * SEQLEN;
    float s = 0.f;
#pragma unroll 4
    for (int l = 0; l < SEQLEN; l++) {
        const int m = mbase + l;
        const float dl = dch[l];
        const float uu = uch[l];
        const float Bn = g_xdbl[(size_t)m * NXPROJ + DTRANK + n];
        const float Cn = g_xdbl[(size_t)m * NXPROJ + DTRANK + DSTATE + n];
        s = fmaf(__expf(dl * a), s, dl * uu * Bn);
        float c = s * Cn;
        c += __shfl_xor_sync(0xffffffffu, c, 8);
        c += __shfl_xor_sync(0xffffffffu, c, 4);
        c += __shfl_xor_sync(0xffffffffu, c, 2);
        c += __shfl_xor_sync(0xffffffffu, c, 1);
        if (n == 0) g_y[(size_t)m * DINNER + d] = c;
    }
}

// ---------------- gating: y2 = (y + u*D) * silu(z) ----------------
__global__ void gate_kernel(const float* __restrict__ Dv)
{
    const int idx = blockIdx.x * blockDim.x + threadIdx.x;
    const int m = idx >> 11, d = idx & 2047;
    const float z = g_xz[(size_t)m * (2 * DINNER) + DINNER + d];
    g_y2[idx] = (g_y[idx] + g_u[idx] * Dv[d]) * siluf(z);
}

// ---------------- launcher ----------------
extern "C" void kernel_launch(void* const* d_in, const int* in_sizes, int n_in,
                              void* d_out, int out_size)
{
    const float* hs      = (const float*)d_in[0];  // [2,1024,1024]
    const float* inW     = (const float*)d_in[1];  // [4096,1024]
    const float* convW   = (const float*)d_in[2];  // [2048,1,4]
    const float* convB   = (const float*)d_in[3];  // [2048]
    const float* xprojW  = (const float*)d_in[4];  // [96,2048]
    const float* dtW     = (const float*)d_in[5];  // [2048,64]
    const float* dtB     = (const float*)d_in[6];  // [2048]
    const float* A_log   = (const float*)d_in[7];  // [2048,16]
    const float* Dv      = (const float*)d_in[8];  // [2048]
    const float* outW    = (const float*)d_in[9];  // [1024,2048]
    float* out = (float*)d_out;

    float *p_xz, *p_y2;
    __nv_bfloat16 *p_hsH, *p_hsL, *p_inWH, *p_inWL, *p_y2H, *p_y2L, *p_outWH, *p_outWL;
    cudaGetSymbolAddress((void**)&p_xz,    g_xz);
    cudaGetSymbolAddress((void**)&p_y2,    g_y2);
    cudaGetSymbolAddress((void**)&p_hsH,   g_hsH);
    cudaGetSymbolAddress((void**)&p_hsL,   g_hsL);
    cudaGetSymbolAddress((void**)&p_inWH,  g_inWH);
    cudaGetSymbolAddress((void**)&p_inWL,  g_inWL);
    cudaGetSymbolAddress((void**)&p_y2H,   g_y2H);
    cudaGetSymbolAddress((void**)&p_y2L,   g_y2L);
    cudaGetSymbolAddress((void**)&p_outWH, g_outWH);
    cudaGetSymbolAddress((void**)&p_outWL, g_outWL);

    static bool attr_set = false;
    if (!attr_set) {
        cudaFuncSetAttribute(mma_gemm, cudaFuncAttributeMaxDynamicSharedMemorySize, GEMM_SMEM);
        attr_set = true;
    }

    // 0) split inputs to hi/lo bf16
    split_kernel<<<(MTOT * DMODEL / 4) / 256, 256>>>(hs, p_hsH, p_hsL);
    split_kernel<<<(2 * DINNER * DMODEL / 4) / 256, 256>>>(inW, p_inWH, p_inWL);
    split_kernel<<<(DMODEL * DINNER / 4) / 256, 256>>>(outW, p_outWH, p_outWL);

    // 1) xz = hs @ in_proj_w^T : [2048,1024] x [4096,1024]^T (tensor cores)
    mma_gemm<<<dim3(2 * DINNER / 128, MTOT / 128), 256, GEMM_SMEM>>>(
        p_hsH, p_hsL, p_inWH, p_inWL, p_xz, 2 * DINNER, DMODEL);

    // 2) causal depthwise conv + SiLU -> u, uT
    conv_silu_kernel<<<dim3(MTOT / 32, DINNER / 32), 256>>>(convW, convB);

    // 3) x_dbl = u @ x_proj_w^T
    gemm_xdbl_kernel<<<MTOT / 32, 256>>>(xprojW);

    // 4) delta (transposed layout)
    dt_delta_kernel<<<dim3(MTOT / 32, DINNER / 32), 256>>>(dtW, dtB);

    // 5) selective scan
    scan_kernel<<<(BATCH * DINNER / 2) / 8, 256>>>(A_log);   // 2048 warps

    // 6) gating
    gate_kernel<<<(MTOT * DINNER) / 256, 256>>>(Dv);

    // 7) out = y2 @ out_proj_w^T (tensor cores)
    split_kernel<<<(MTOT * DINNER / 4) / 256, 256>>>(p_y2, p_y2H, p_y2L);
    mma_gemm<<<dim3(DMODEL / 128, MTOT / 128), 256, GEMM_SMEM>>>(
        p_y2H, p_y2L, p_outWH, p_outWL, out, DMODEL, DINNER);
}

// round 6
// speedup vs baseline: 1.7856x; 1.1659x over previous
#include <cuda_runtime.h>
#include <cuda_bf16.h>
#include <math.h>
#include <stdint.h>

// ---------------- problem constants ----------------
#define BATCH   2
#define SEQLEN  1024
#define DMODEL  1024
#define DINNER  2048
#define DSTATE  16
#define DTRANK  64
#define MTOT    (BATCH*SEQLEN)        // 2048 rows (b*L + l)
#define NXPROJ  (DTRANK + 2*DSTATE)   // 96

// ---------------- scratch (device globals; no allocation) ----------------
__device__ float g_xz   [MTOT * 2*DINNER];  // [m, 4096]  x | z
__device__ float g_u    [MTOT * DINNER];    // [m, d]     conv+silu output
__device__ float g_uT   [BATCH * DINNER * SEQLEN]; // [(b*2048+d), l]
__device__ float g_xdbl [MTOT * NXPROJ];    // [m, 96]    dt_low | B | C
__device__ float g_xpart[4 * MTOT * NXPROJ];// split-K partials
__device__ float g_dT   [BATCH * DINNER * SEQLEN]; // delta transposed
__device__ float g_y    [MTOT * DINNER];    // scan output [m, d]

// split-bf16 operands (row-major hi / lo)
__device__ __nv_bfloat16 g_hsH  [MTOT * DMODEL],      g_hsL  [MTOT * DMODEL];
__device__ __nv_bfloat16 g_inWH [2*DINNER * DMODEL],  g_inWL [2*DINNER * DMODEL];
__device__ __nv_bfloat16 g_y2H  [MTOT * DINNER],      g_y2L  [MTOT * DINNER];
__device__ __nv_bfloat16 g_outWH[DMODEL * DINNER],    g_outWL[DMODEL * DINNER];

__device__ __forceinline__ float siluf(float x) { return x / (1.f + __expf(-x)); }

// ================= mma helpers (sm_80-compatible PTX) =================
#define MMA_BF16(d, a, b)                                                     \
    asm volatile("mma.sync.aligned.m16n8k16.row.col.f32.bf16.bf16.f32 "       \
        "{%0,%1,%2,%3}, {%4,%5,%6,%7}, {%8,%9}, {%0,%1,%2,%3};"               \
        : "+f"((d)[0]), "+f"((d)[1]), "+f"((d)[2]), "+f"((d)[3])              \
        : "r"((a)[0]), "r"((a)[1]), "r"((a)[2]), "r"((a)[3]),                 \
          "r"((b)[0]), "r"((b)[1]))

#define LDSM4(r, addr)                                                        \
    asm volatile("ldmatrix.sync.aligned.m8n8.x4.shared.b16 {%0,%1,%2,%3}, [%4];" \
        : "=r"((r)[0]), "=r"((r)[1]), "=r"((r)[2]), "=r"((r)[3]) : "r"(addr))

#define CP_ASYNC16(s, g)                                                      \
    asm volatile("cp.async.cg.shared.global [%0], [%1], 16;" :: "r"(s), "l"(g))

// ---------------- split fp32 -> (hi,lo) bf16 row-major ----------------
__global__ void split_kernel(const float* __restrict__ src,
                             __nv_bfloat16* __restrict__ hi,
                             __nv_bfloat16* __restrict__ lo)
{
    const int idx = blockIdx.x * blockDim.x + threadIdx.x;   // elems/4
    float4 v = ((const float4*)src)[idx];
    float f[4] = {v.x, v.y, v.z, v.w};
    union { __nv_bfloat16 h[4]; uint2 u; } H, L;
#pragma unroll
    for (int i = 0; i < 4; i++) {
        __nv_bfloat16 hh = __float2bfloat16(f[i]);
        H.h[i] = hh;
        L.h[i] = __float2bfloat16(f[i] - __bfloat162float(hh));
    }
    ((uint2*)hi)[idx] = H.u;
    ((uint2*)lo)[idx] = L.u;
}

// ---------------- 3-term split-bf16 MMA GEMM: C[m,n] = A[m,:]·B[n,:] (NT) ----------------
// CTA tile 128 x BN, BK=32, 8 warps (4m x 2n), cp.async double buffer, 2 CTAs/SM.
template<int BN>
__global__ __launch_bounds__(256, 2) void mma_gemm(
    const __nv_bfloat16* __restrict__ Ah, const __nv_bfloat16* __restrict__ Al,
    const __nv_bfloat16* __restrict__ Bh, const __nv_bfloat16* __restrict__ Bl,
    float* __restrict__ C, int N, int K)
{
    constexpr int NT    = BN / 16;           // n8-frags per warp
    constexpr int AMATB = 128 * 40 * 2;      // bytes per A matrix tile (10240)
    constexpr int BMATB = BN  * 40 * 2;      // bytes per B matrix tile
    constexpr int BUFB_ = 2 * AMATB + 2 * BMATB;

    extern __shared__ __align__(128) char smem[];
    const uint32_t sb = (uint32_t)__cvta_generic_to_shared(smem);
    const int tid = threadIdx.x, lane = tid & 31, wid = tid >> 5;
    const int wm = wid >> 1, wn = wid & 1;
    const int m0 = blockIdx.y * 128, n0 = blockIdx.x * BN;
    const int KT = K >> 5;

    const __nv_bfloat16* gAh = Ah + (size_t)m0 * K;
    const __nv_bfloat16* gAl = Al + (size_t)m0 * K;
    const __nv_bfloat16* gBh = Bh + (size_t)n0 * K;
    const __nv_bfloat16* gBl = Bl + (size_t)n0 * K;

    const int lrow = tid >> 2;            // 0..63
    const int lcol = (tid & 3) * 8;

    float acc[2][NT][4];
#pragma unroll
    for (int i = 0; i < 2; i++)
#pragma unroll
        for (int j = 0; j < NT; j++)
#pragma unroll
            for (int q = 0; q < 4; q++) acc[i][j][q] = 0.f;

    auto load_tile = [&](int ktIdx, int buf) {
        const int kO = ktIdx * 32;
        const uint32_t sB = sb + buf * BUFB_;
        CP_ASYNC16(sB + (lrow * 40 + lcol) * 2,        gAh + (size_t)lrow * K + kO + lcol);
        CP_ASYNC16(sB + ((lrow + 64) * 40 + lcol) * 2, gAh + (size_t)(lrow + 64) * K + kO + lcol);
        CP_ASYNC16(sB + AMATB + (lrow * 40 + lcol) * 2,        gAl + (size_t)lrow * K + kO + lcol);
        CP_ASYNC16(sB + AMATB + ((lrow + 64) * 40 + lcol) * 2, gAl + (size_t)(lrow + 64) * K + kO + lcol);
        CP_ASYNC16(sB + 2 * AMATB + (lrow * 40 + lcol) * 2, gBh + (size_t)lrow * K + kO + lcol);
        CP_ASYNC16(sB + 2 * AMATB + BMATB + (lrow * 40 + lcol) * 2, gBl + (size_t)lrow * K + kO + lcol);
        if (BN == 128) {
            CP_ASYNC16(sB + 2 * AMATB + ((lrow + 64) * 40 + lcol) * 2,
                       gBh + (size_t)(lrow + 64) * K + kO + lcol);
            CP_ASYNC16(sB + 2 * AMATB + BMATB + ((lrow + 64) * 40 + lcol) * 2,
                       gBl + (size_t)(lrow + 64) * K + kO + lcol);
        }
        asm volatile("cp.async.commit_group;" ::: "memory");
    };

    load_tile(0, 0);

    const int arow  = wm * 32 + (lane & 15);
    const int acolb = (lane >> 4) * 8;
    const int brow  = wn * (BN / 2) + (lane & 7) + ((lane >> 4) << 3);
    const int bcolb = ((lane >> 3) & 1) * 8;

    for (int kt = 0; kt < KT; kt++) {
        const int buf = kt & 1;
        if (kt + 1 < KT) {
            load_tile(kt + 1, (kt + 1) & 1);
            asm volatile("cp.async.wait_group 1;" ::: "memory");
        } else {
            asm volatile("cp.async.wait_group 0;" ::: "memory");
        }
        __syncthreads();

        const uint32_t base = sb + buf * BUFB_;
#pragma unroll
        for (int ks = 0; ks < 2; ks++) {
            uint32_t aH[2][4], aL[2][4];
            const int acol = ks * 16 + acolb;
            LDSM4(aH[0], base + ((arow)      * 40 + acol) * 2);
            LDSM4(aH[1], base + ((arow + 16) * 40 + acol) * 2);
            LDSM4(aL[0], base + AMATB + ((arow)      * 40 + acol) * 2);
            LDSM4(aL[1], base + AMATB + ((arow + 16) * 40 + acol) * 2);
            const int bcol = ks * 16 + bcolb;
#pragma unroll
            for (int p = 0; p < NT / 2; p++) {
                uint32_t bh[4], bl[4];
                LDSM4(bh, base + 2 * AMATB + ((brow + p * 16) * 40 + bcol) * 2);
                LDSM4(bl, base + 2 * AMATB + BMATB + ((brow + p * 16) * 40 + bcol) * 2);
#pragma unroll
                for (int mt = 0; mt < 2; mt++) {
                    MMA_BF16(acc[mt][2 * p],     aH[mt], bh);
                    MMA_BF16(acc[mt][2 * p],     aL[mt], bh);
                    MMA_BF16(acc[mt][2 * p],     aH[mt], bl);
                    MMA_BF16(acc[mt][2 * p + 1], aH[mt], bh + 2);
                    MMA_BF16(acc[mt][2 * p + 1], aL[mt], bh + 2);
                    MMA_BF16(acc[mt][2 * p + 1], aH[mt], bl + 2);
                }
            }
        }
        __syncthreads();
    }

    // epilogue
#pragma unroll
    for (int mt = 0; mt < 2; mt++) {
        const int row = m0 + wm * 32 + mt * 16 + (lane >> 2);
#pragma unroll
        for (int nt = 0; nt < NT; nt++) {
            const int col = n0 + wn * (BN / 2) + nt * 8 + (lane & 3) * 2;
            *(float2*)&C[(size_t)row * N + col] =
                make_float2(acc[mt][nt][0], acc[mt][nt][1]);
            *(float2*)&C[(size_t)(row + 8) * N + col] =
                make_float2(acc[mt][nt][2], acc[mt][nt][3]);
        }
    }
}

#define GEMM1_SMEM (2 * (2 * 128 * 80 + 2 * 128 * 80))   // 81920
#define GEMM4_SMEM (2 * (2 * 128 * 80 + 2 * 64 * 80))    // 61440

// ---------------- causal depthwise conv (K=4) + SiLU; write u and u^T ----------------
__global__ void conv_silu_kernel(const float* __restrict__ cw, const float* __restrict__ cb)
{
    __shared__ float Ts[32][33];
    const int tid = threadIdx.x;                 // 256
    const int m0 = blockIdx.x * 32, d0 = blockIdx.y * 32;
    const int b = m0 >> 10;
    const int l0 = m0 & 1023;
    const int di = tid & 31, lg = tid >> 5;
    const int d = d0 + di;
    const float w0 = cw[d * 4 + 0], w1 = cw[d * 4 + 1];
    const float w2 = cw[d * 4 + 2], w3 = cw[d * 4 + 3];
    const float bias = cb[d];
#pragma unroll
    for (int j = 0; j < 4; j++) {
        const int li = lg * 4 + j;
        const int l = l0 + li;
        const int m = m0 + li;
        float s = bias;
        const float* xcol = g_xz + (size_t)m * (2 * DINNER) + d;
        if (l >= 3) s = fmaf(xcol[-3 * 2 * DINNER], w0, s);
        if (l >= 2) s = fmaf(xcol[-2 * 2 * DINNER], w1, s);
        if (l >= 1) s = fmaf(xcol[-1 * 2 * DINNER], w2, s);
        s = fmaf(xcol[0], w3, s);
        const float uv = siluf(s);
        g_u[(size_t)m * DINNER + d] = uv;
        Ts[li][di] = uv;
    }
    __syncthreads();
    const int li2 = tid & 31, dg = tid >> 5;
#pragma unroll
    for (int j = 0; j < 4; j++) {
        const int di2 = dg * 4 + j;
        g_uT[(size_t)(b * DINNER + d0 + di2) * SEQLEN + l0 + li2] = Ts[li2][di2];
    }
}

// ---------------- x_dbl partials: split-K=4 over K=2048 ----------------
__global__ void gemm_xdbl_kernel(const float* __restrict__ W)
{
    __shared__ float Us[32][33];
    __shared__ float Ws[96][33];
    const int tid = threadIdx.x;            // 256
    const int m0 = blockIdx.x * 32;
    const int ks = blockIdx.y;              // 0..3
    const int tn = tid & 15, tm = tid >> 4;
    float acc[2][6];
#pragma unroll
    for (int i = 0; i < 2; i++)
#pragma unroll
        for (int j = 0; j < 6; j++) acc[i][j] = 0.f;

    const int ulr = tid >> 3, ulc = (tid & 7) << 2;
    const int kend = ks * 512 + 512;
    for (int k0 = ks * 512; k0 < kend; k0 += 32) {
        float4 uv = *(const float4*)(g_u + (size_t)(m0 + ulr) * DINNER + k0 + ulc);
        Us[ulr][ulc + 0] = uv.x; Us[ulr][ulc + 1] = uv.y;
        Us[ulr][ulc + 2] = uv.z; Us[ulr][ulc + 3] = uv.w;
#pragma unroll
        for (int i = 0; i < 3; i++) {
            int idx = tid + i * 256;
            int wr = idx >> 3, wc = (idx & 7) << 2;
            float4 wv = *(const float4*)(W + (size_t)wr * DINNER + k0 + wc);
            Ws[wr][wc + 0] = wv.x; Ws[wr][wc + 1] = wv.y;
            Ws[wr][wc + 2] = wv.z; Ws[wr][wc + 3] = wv.w;
        }
        __syncthreads();
#pragma unroll 8
        for (int k = 0; k < 32; k++) {
            float u0 = Us[tm * 2 + 0][k];
            float u1 = Us[tm * 2 + 1][k];
#pragma unroll
            for (int j = 0; j < 6; j++) {
                float w = Ws[tn * 6 + j][k];
                acc[0][j] = fmaf(u0, w, acc[0][j]);
                acc[1][j] = fmaf(u1, w, acc[1][j]);
            }
        }
        __syncthreads();
    }
    float* dst = g_xpart + (size_t)ks * MTOT * NXPROJ;
#pragma unroll
    for (int i = 0; i < 2; i++)
#pragma unroll
        for (int j = 0; j < 6; j++)
            dst[(size_t)(m0 + tm * 2 + i) * NXPROJ + tn * 6 + j] = acc[i][j];
}

__global__ void xdbl_reduce_kernel()
{
    const int idx = blockIdx.x * blockDim.x + threadIdx.x;  // float4 idx < 49152
    const float4* p = (const float4*)g_xpart;
    const int S = MTOT * NXPROJ / 4;
    float4 a = p[idx], b = p[idx + S], c = p[idx + 2 * S], d = p[idx + 3 * S];
    ((float4*)g_xdbl)[idx] = make_float4(a.x + b.x + c.x + d.x, a.y + b.y + c.y + d.y,
                                         a.z + b.z + c.z + d.z, a.w + b.w + c.w + d.w);
}

// ---------------- delta (transposed): softplus(dt_low @ dt_w^T + 2*dt_b) ----------------
// tile 64 l x 64 d, k-major smem, 4x4 thread tile
__global__ void dt_delta_kernel(const float* __restrict__ Wd, const float* __restrict__ bd)
{
    __shared__ float XsT[64][68];
    __shared__ float WsT[64][68];
    const int tid = threadIdx.x;                     // 256
    const int m0 = blockIdx.x * 64, d0 = blockIdx.y * 64;
    const int r = tid & 63, cb = tid >> 6;           // cb 0..3
#pragma unroll
    for (int q = 0; q < 4; q++) {
        const int c = cb * 16 + q * 4;
        float4 xv = *(const float4*)(g_xdbl + (size_t)(m0 + r) * NXPROJ + c);
        XsT[c + 0][r] = xv.x; XsT[c + 1][r] = xv.y;
        XsT[c + 2][r] = xv.z; XsT[c + 3][r] = xv.w;
        float4 wv = *(const float4*)(Wd + (size_t)(d0 + r) * DTRANK + c);
        WsT[c + 0][r] = wv.x; WsT[c + 1][r] = wv.y;
        WsT[c + 2][r] = wv.z; WsT[c + 3][r] = wv.w;
    }
    __syncthreads();
    const int tx = tid & 15, ty = tid >> 4;
    float acc[4][4];
#pragma unroll
    for (int i = 0; i < 4; i++)
#pragma unroll
        for (int j = 0; j < 4; j++) acc[i][j] = 0.f;
#pragma unroll 8
    for (int k = 0; k < 64; k++) {
        float4 xv = *(const float4*)&XsT[k][ty * 4];
        float4 wv = *(const float4*)&WsT[k][tx * 4];
        float xa[4] = {xv.x, xv.y, xv.z, xv.w};
        float wa[4] = {wv.x, wv.y, wv.z, wv.w};
#pragma unroll
        for (int i = 0; i < 4; i++)
#pragma unroll
            for (int j = 0; j < 4; j++)
                acc[i][j] = fmaf(xa[i], wa[j], acc[i][j]);
    }
    const int b = m0 >> 10;
    const int lb = (m0 & 1023) + ty * 4;
#pragma unroll
    for (int j = 0; j < 4; j++) {
        const int d = d0 + tx * 4 + j;
        const float b2 = 2.f * bd[d];
        float* drow = g_dT + (size_t)(b * DINNER + d) * SEQLEN;
#pragma unroll
        for (int i = 0; i < 4; i++) {
            float x = acc[i][j] + b2;
            float sp = (x > 20.f) ? x : log1pf(__expf(x));
            drow[lb + i] = sp;
        }
    }
}

// ---------------- selective scan: lane-per-state, 2 channels per warp ----------------
__global__ void scan_kernel(const float* __restrict__ A_log)
{
    const int warp = (blockIdx.x * blockDim.x + threadIdx.x) >> 5;
    const int lane = threadIdx.x & 31;
    const int b = warp >> 10;
    const int dp = warp & 1023;
    const int half = lane >> 4, n = lane & 15;
    const int d = dp * 2 + half;
    const int ch = b * DINNER + d;
    const float a = -__expf(A_log[d * DSTATE + n]);
    const float* dch = g_dT + (size_t)ch * SEQLEN;
    const float* uch = g_uT + (size_t)ch * SEQLEN;
    const int mbase = b * SEQLEN;
    float s = 0.f;
#pragma unroll 4
    for (int l = 0; l < SEQLEN; l++) {
        const int m = mbase + l;
        const float dl = dch[l];
        const float uu = uch[l];
        const float Bn = g_xdbl[(size_t)m * NXPROJ + DTRANK + n];
        const float Cn = g_xdbl[(size_t)m * NXPROJ + DTRANK + DSTATE + n];
        s = fmaf(__expf(dl * a), s, dl * uu * Bn);
        float c = s * Cn;
        c += __shfl_xor_sync(0xffffffffu, c, 8);
        c += __shfl_xor_sync(0xffffffffu, c, 4);
        c += __shfl_xor_sync(0xffffffffu, c, 2);
        c += __shfl_xor_sync(0xffffffffu, c, 1);
        if (n == 0) g_y[(size_t)m * DINNER + d] = c;
    }
}

// ---------------- gating fused with bf16 split: y2H/L = split((y + u*D) * silu(z)) ----------------
__global__ void gate_split_kernel(const float* __restrict__ Dv)
{
    const int i4 = blockIdx.x * blockDim.x + threadIdx.x;   // float4 idx < MTOT*DINNER/4
    const int m = (i4 * 4) >> 11, d = (i4 * 4) & 2047;
    float4 y = ((const float4*)g_y)[i4];
    float4 u = ((const float4*)g_u)[i4];
    float4 z = *(const float4*)(g_xz + (size_t)m * (2 * DINNER) + DINNER + d);
    float4 dv = *(const float4*)(Dv + d);
    float v[4];
    v[0] = (y.x + u.x * dv.x) * siluf(z.x);
    v[1] = (y.y + u.y * dv.y) * siluf(z.y);
    v[2] = (y.z + u.z * dv.z) * siluf(z.z);
    v[3] = (y.w + u.w * dv.w) * siluf(z.w);
    union { __nv_bfloat16 h[4]; uint2 u2; } H, L;
#pragma unroll
    for (int i = 0; i < 4; i++) {
        __nv_bfloat16 hh = __float2bfloat16(v[i]);
        H.h[i] = hh;
        L.h[i] = __float2bfloat16(v[i] - __bfloat162float(hh));
    }
    ((uint2*)g_y2H)[i4] = H.u2;
    ((uint2*)g_y2L)[i4] = L.u2;
}

// ---------------- launcher ----------------
extern "C" void kernel_launch(void* const* d_in, const int* in_sizes, int n_in,
                              void* d_out, int out_size)
{
    const float* hs      = (const float*)d_in[0];  // [2,1024,1024]
    const float* inW     = (const float*)d_in[1];  // [4096,1024]
    const float* convW   = (const float*)d_in[2];  // [2048,1,4]
    const float* convB   = (const float*)d_in[3];  // [2048]
    const float* xprojW  = (const float*)d_in[4];  // [96,2048]
    const float* dtW     = (const float*)d_in[5];  // [2048,64]
    const float* dtB     = (const float*)d_in[6];  // [2048]
    const float* A_log   = (const float*)d_in[7];  // [2048,16]
    const float* Dv      = (const float*)d_in[8];  // [2048]
    const float* outW    = (const float*)d_in[9];  // [1024,2048]
    float* out = (float*)d_out;

    float* p_xz;
    __nv_bfloat16 *p_hsH, *p_hsL, *p_inWH, *p_inWL, *p_y2H, *p_y2L, *p_outWH, *p_outWL;
    cudaGetSymbolAddress((void**)&p_xz,    g_xz);
    cudaGetSymbolAddress((void**)&p_hsH,   g_hsH);
    cudaGetSymbolAddress((void**)&p_hsL,   g_hsL);
    cudaGetSymbolAddress((void**)&p_inWH,  g_inWH);
    cudaGetSymbolAddress((void**)&p_inWL,  g_inWL);
    cudaGetSymbolAddress((void**)&p_y2H,   g_y2H);
    cudaGetSymbolAddress((void**)&p_y2L,   g_y2L);
    cudaGetSymbolAddress((void**)&p_outWH, g_outWH);
    cudaGetSymbolAddress((void**)&p_outWL, g_outWL);

    static bool attr_set = false;
    if (!attr_set) {
        cudaFuncSetAttribute(mma_gemm<128>, cudaFuncAttributeMaxDynamicSharedMemorySize, GEMM1_SMEM);
        cudaFuncSetAttribute(mma_gemm<64>,  cudaFuncAttributeMaxDynamicSharedMemorySize, GEMM4_SMEM);
        attr_set = true;
    }

    // 0) split inputs to hi/lo bf16
    split_kernel<<<(MTOT * DMODEL / 4) / 256, 256>>>(hs, p_hsH, p_hsL);
    split_kernel<<<(2 * DINNER * DMODEL / 4) / 256, 256>>>(inW, p_inWH, p_inWL);
    split_kernel<<<(DMODEL * DINNER / 4) / 256, 256>>>(outW, p_outWH, p_outWL);

    // 1) xz = hs @ in_proj_w^T : [2048,1024] x [4096,1024]^T (tensor cores, BN=128)
    mma_gemm<128><<<dim3(2 * DINNER / 128, MTOT / 128), 256, GEMM1_SMEM>>>(
        p_hsH, p_hsL, p_inWH, p_inWL, p_xz, 2 * DINNER, DMODEL);

    // 2) causal depthwise conv + SiLU -> u, uT
    conv_silu_kernel<<<dim3(MTOT / 32, DINNER / 32), 256>>>(convW, convB);

    // 3) x_dbl = u @ x_proj_w^T (split-K=4 + reduce)
    gemm_xdbl_kernel<<<dim3(MTOT / 32, 4), 256>>>(xprojW);
    xdbl_reduce_kernel<<<(MTOT * NXPROJ / 4) / 256, 256>>>();

    // 4) delta (transposed layout)
    dt_delta_kernel<<<dim3(MTOT / 64, DINNER / 64), 256>>>(dtW, dtB);

    // 5) selective scan
    scan_kernel<<<(BATCH * DINNER / 2) / 8, 256>>>(A_log);   // 2048 warps

    // 6) gating + bf16 split (fused)
    gate_split_kernel<<<(MTOT * DINNER / 4) / 256, 256>>>(Dv);

    // 7) out = y2 @ out_proj_w^T (tensor cores, BN=64 -> 256 CTAs)
    mma_gemm<64><<<dim3(DMODEL / 64, MTOT / 128), 256, GEMM4_SMEM>>>(
        p_y2H, p_y2L, p_outWH, p_outWL, out, DMODEL, DINNER);
}

// round 7
// speedup vs baseline: 1.8001x; 1.0081x over previous
#include <cuda_runtime.h>
#include <cuda_bf16.h>
#include <math.h>
#include <stdint.h>

// ---------------- problem constants ----------------
#define BATCH   2
#define SEQLEN  1024
#define DMODEL  1024
#define DINNER  2048
#define DSTATE  16
#define DTRANK  64
#define MTOT    (BATCH*SEQLEN)        // 2048 rows (b*L + l)
#define NXPROJ  (DTRANK + 2*DSTATE)   // 96

// ---------------- scratch (device globals; no allocation) ----------------
__device__ float g_xz   [MTOT * 2*DINNER];  // [m, 4096]  x | z
__device__ float g_u    [MTOT * DINNER];    // [m, d]     conv+silu output
__device__ float g_uT   [BATCH * DINNER * SEQLEN]; // [(b*2048+d), l]
__device__ float g_xdbl [MTOT * NXPROJ];    // [m, 96]    dt_low | B | C
__device__ float g_xpart[4 * MTOT * NXPROJ];// split-K partials
__device__ float g_dT   [BATCH * DINNER * SEQLEN]; // delta transposed
__device__ float g_y    [MTOT * DINNER];    // scan output [m, d]

// split-bf16 operands (row-major hi / lo)
__device__ __nv_bfloat16 g_hsH  [MTOT * DMODEL],      g_hsL  [MTOT * DMODEL];
__device__ __nv_bfloat16 g_inWH [2*DINNER * DMODEL],  g_inWL [2*DINNER * DMODEL];
__device__ __nv_bfloat16 g_y2H  [MTOT * DINNER],      g_y2L  [MTOT * DINNER];
__device__ __nv_bfloat16 g_outWH[DMODEL * DINNER],    g_outWL[DMODEL * DINNER];

__device__ __forceinline__ float siluf(float x) { return x / (1.f + __expf(-x)); }

// ================= mma helpers (sm_80-compatible PTX) =================
#define MMA_BF16(d, a, b)                                                     \
    asm volatile("mma.sync.aligned.m16n8k16.row.col.f32.bf16.bf16.f32 "       \
        "{%0,%1,%2,%3}, {%4,%5,%6,%7}, {%8,%9}, {%0,%1,%2,%3};"               \
        : "+f"((d)[0]), "+f"((d)[1]), "+f"((d)[2]), "+f"((d)[3])              \
        : "r"((a)[0]), "r"((a)[1]), "r"((a)[2]), "r"((a)[3]),                 \
          "r"((b)[0]), "r"((b)[1]))

#define LDSM4(r, addr)                                                        \
    asm volatile("ldmatrix.sync.aligned.m8n8.x4.shared.b16 {%0,%1,%2,%3}, [%4];" \
        : "=r"((r)[0]), "=r"((r)[1]), "=r"((r)[2]), "=r"((r)[3]) : "r"(addr))

#define CP_ASYNC16(s, g)                                                      \
    asm volatile("cp.async.cg.shared.global [%0], [%1], 16;" :: "r"(s), "l"(g))

// byte offset in a [rows x 32 bf16] tile with XOR swizzle (conflict-free)
__device__ __forceinline__ uint32_t swz(int r, int c) {
    return (uint32_t)(r * 64 + ((c ^ ((r >> 1) & 3)) << 4));
}

// ---------------- split fp32 -> (hi,lo) bf16 row-major ----------------
__global__ void split_kernel(const float* __restrict__ src,
                             __nv_bfloat16* __restrict__ hi,
                             __nv_bfloat16* __restrict__ lo)
{
    const int idx = blockIdx.x * blockDim.x + threadIdx.x;   // elems/4
    float4 v = ((const float4*)src)[idx];
    float f[4] = {v.x, v.y, v.z, v.w};
    union { __nv_bfloat16 h[4]; uint2 u; } H, L;
#pragma unroll
    for (int i = 0; i < 4; i++) {
        __nv_bfloat16 hh = __float2bfloat16(f[i]);
        H.h[i] = hh;
        L.h[i] = __float2bfloat16(f[i] - __bfloat162float(hh));
    }
    ((uint2*)hi)[idx] = H.u;
    ((uint2*)lo)[idx] = L.u;
}

// ---------------- 3-term split-bf16 MMA GEMM: C[m,n] = A[m,:]·B[n,:] (NT) ----------------
// CTA 128 x BN, BK=32, 8 warps (4m x 2n), 3-stage cp.async ring, 1 barrier/iter.
template<int BN>
__global__ __launch_bounds__(256, 2) void mma_gemm(
    const __nv_bfloat16* __restrict__ Ah, const __nv_bfloat16* __restrict__ Al,
    const __nv_bfloat16* __restrict__ Bh, const __nv_bfloat16* __restrict__ Bl,
    float* __restrict__ C, int N, int K)
{
    constexpr int NT     = BN / 16;
    constexpr int AMATB  = 128 * 64;          // 8192 B per A matrix tile
    constexpr int BMATB  = BN * 64;           // B matrix tile bytes
    constexpr int STAGEB = 2 * AMATB + 2 * BMATB;

    extern __shared__ __align__(128) char smem[];
    const uint32_t sb = (uint32_t)__cvta_generic_to_shared(smem);
    const int tid = threadIdx.x, lane = tid & 31, wid = tid >> 5;
    const int wm = wid >> 1, wn = wid & 1;
    const int m0 = blockIdx.y * 128, n0 = blockIdx.x * BN;
    const int KT = K >> 5;

    const __nv_bfloat16* gAh = Ah + (size_t)m0 * K;
    const __nv_bfloat16* gAl = Al + (size_t)m0 * K;
    const __nv_bfloat16* gBh = Bh + (size_t)n0 * K;
    const __nv_bfloat16* gBl = Bl + (size_t)n0 * K;

    // load mapping: A (128 rows x 4 chunks): 2 chunks/thread/matrix
    const int ar = tid >> 1, ac = (tid & 1) * 2;
    // B: BN==128 -> same as A; BN==64 -> 1 chunk/thread/matrix
    const int br = (BN == 128) ? (tid >> 1) : (tid >> 2);
    const int bc = (BN == 128) ? (tid & 1) * 2 : (tid & 3);

    float acc[2][NT][4];
#pragma unroll
    for (int i = 0; i < 2; i++)
#pragma unroll
        for (int j = 0; j < NT; j++)
#pragma unroll
            for (int q = 0; q < 4; q++) acc[i][j][q] = 0.f;

    auto load_tile = [&](int ktIdx, int stage) {
        const int kO = ktIdx * 32;
        const uint32_t sB = sb + stage * STAGEB;
        CP_ASYNC16(sB + swz(ar, ac),             gAh + (size_t)ar * K + kO + ac * 8);
        CP_ASYNC16(sB + swz(ar, ac + 1),         gAh + (size_t)ar * K + kO + ac * 8 + 8);
        CP_ASYNC16(sB + AMATB + swz(ar, ac),     gAl + (size_t)ar * K + kO + ac * 8);
        CP_ASYNC16(sB + AMATB + swz(ar, ac + 1), gAl + (size_t)ar * K + kO + ac * 8 + 8);
        if (BN == 128) {
            CP_ASYNC16(sB + 2 * AMATB + swz(br, bc),             gBh + (size_t)br * K + kO + bc * 8);
            CP_ASYNC16(sB + 2 * AMATB + swz(br, bc + 1),         gBh + (size_t)br * K + kO + bc * 8 + 8);
            CP_ASYNC16(sB + 2 * AMATB + BMATB + swz(br, bc),     gBl + (size_t)br * K + kO + bc * 8);
            CP_ASYNC16(sB + 2 * AMATB + BMATB + swz(br, bc + 1), gBl + (size_t)br * K + kO + bc * 8 + 8);
        } else {
            CP_ASYNC16(sB + 2 * AMATB + swz(br, bc),         gBh + (size_t)br * K + kO + bc * 8);
            CP_ASYNC16(sB + 2 * AMATB + BMATB + swz(br, bc), gBl + (size_t)br * K + kO + bc * 8);
        }
        asm volatile("cp.async.commit_group;" ::: "memory");
    };

    load_tile(0, 0);
    load_tile(1, 1);

    const int arow  = wm * 32 + (lane & 15);
    const int achb  = lane >> 4;             // chunk half 0/1
    const int qA    = (arow >> 1) & 3;       // same for arow and arow+16
    const int brow  = wn * (BN / 2) + (lane & 7) + ((lane >> 4) << 3);
    const int bchb  = (lane >> 3) & 1;
    const int qB    = (brow >> 1) & 3;       // same for brow + p*16

    int stage = 0;
    for (int kt = 0; kt < KT; kt++) {
        asm volatile("cp.async.wait_group 1;" ::: "memory");
        __syncthreads();     // publishes stage kt; also retires WAR on ring reuse
        if (kt + 2 < KT) {
            int ns = stage + 2; if (ns >= 3) ns -= 3;
            load_tile(kt + 2, ns);
        }
        const uint32_t base = sb + stage * STAGEB;
#pragma unroll
        for (int ks = 0; ks < 2; ks++) {
            uint32_t aH[2][4], aL[2][4];
            const uint32_t acoff = (uint32_t)(((ks * 2 + achb) ^ qA) << 4);
            LDSM4(aH[0], base + (uint32_t)(arow * 64) + acoff);
            LDSM4(aH[1], base + (uint32_t)((arow + 16) * 64) + acoff);
            LDSM4(aL[0], base + AMATB + (uint32_t)(arow * 64) + acoff);
            LDSM4(aL[1], base + AMATB + (uint32_t)((arow + 16) * 64) + acoff);
            const uint32_t bcoff = (uint32_t)(((ks * 2 + bchb) ^ qB) << 4);
#pragma unroll
            for (int p = 0; p < NT / 2; p++) {
                uint32_t bh[4], bl[4];
                LDSM4(bh, base + 2 * AMATB + (uint32_t)((brow + p * 16) * 64) + bcoff);
                LDSM4(bl, base + 2 * AMATB + BMATB + (uint32_t)((brow + p * 16) * 64) + bcoff);
#pragma unroll
                for (int mt = 0; mt < 2; mt++) {
                    MMA_BF16(acc[mt][2 * p],     aH[mt], bh);
                    MMA_BF16(acc[mt][2 * p],     aL[mt], bh);
                    MMA_BF16(acc[mt][2 * p],     aH[mt], bl);
                    MMA_BF16(acc[mt][2 * p + 1], aH[mt], bh + 2);
                    MMA_BF16(acc[mt][2 * p + 1], aL[mt], bh + 2);
                    MMA_BF16(acc[mt][2 * p + 1], aH[mt], bl + 2);
                }
            }
        }
        if (++stage == 3) stage = 0;
    }

    // epilogue
#pragma unroll
    for (int mt = 0; mt < 2; mt++) {
        const int row = m0 + wm * 32 + mt * 16 + (lane >> 2);
#pragma unroll
        for (int nt = 0; nt < NT; nt++) {
            const int col = n0 + wn * (BN / 2) + nt * 8 + (lane & 3) * 2;
            *(float2*)&C[(size_t)row * N + col] =
                make_float2(acc[mt][nt][0], acc[mt][nt][1]);
            *(float2*)&C[(size_t)(row + 8) * N + col] =
                make_float2(acc[mt][nt][2], acc[mt][nt][3]);
        }
    }
}

#define GEMM1_SMEM (3 * (2 * 128 * 64 + 2 * 128 * 64))   // 98304
#define GEMM4_SMEM (3 * (2 * 128 * 64 + 2 * 64 * 64))    // 73728

// ---------------- causal depthwise conv (K=4) + SiLU; write u and u^T ----------------
__global__ void conv_silu_kernel(const float* __restrict__ cw, const float* __restrict__ cb)
{
    __shared__ float Ts[32][33];
    const int tid = threadIdx.x;                 // 256
    const int m0 = blockIdx.x * 32, d0 = blockIdx.y * 32;
    const int b = m0 >> 10;
    const int l0 = m0 & 1023;
    const int di = tid & 31, lg = tid >> 5;
    const int d = d0 + di;
    const float w0 = cw[d * 4 + 0], w1 = cw[d * 4 + 1];
    const float w2 = cw[d * 4 + 2], w3 = cw[d * 4 + 3];
    const float bias = cb[d];
#pragma unroll
    for (int j = 0; j < 4; j++) {
        const int li = lg * 4 + j;
        const int l = l0 + li;
        const int m = m0 + li;
        float s = bias;
        const float* xcol = g_xz + (size_t)m * (2 * DINNER) + d;
        if (l >= 3) s = fmaf(xcol[-3 * 2 * DINNER], w0, s);
        if (l >= 2) s = fmaf(xcol[-2 * 2 * DINNER], w1, s);
        if (l >= 1) s = fmaf(xcol[-1 * 2 * DINNER], w2, s);
        s = fmaf(xcol[0], w3, s);
        const float uv = siluf(s);
        g_u[(size_t)m * DINNER + d] = uv;
        Ts[li][di] = uv;
    }
    __syncthreads();
    const int li2 = tid & 31, dg = tid >> 5;
#pragma unroll
    for (int j = 0; j < 4; j++) {
        const int di2 = dg * 4 + j;
        g_uT[(size_t)(b * DINNER + d0 + di2) * SEQLEN + l0 + li2] = Ts[li2][di2];
    }
}

// ---------------- x_dbl partials: split-K=4 over K=2048 ----------------
__global__ void gemm_xdbl_kernel(const float* __restrict__ W)
{
    __shared__ float Us[32][33];
    __shared__ float Ws[96][33];
    const int tid = threadIdx.x;            // 256
    const int m0 = blockIdx.x * 32;
    const int ks = blockIdx.y;              // 0..3
    const int tn = tid & 15, tm = tid >> 4;
    float acc[2][6];
#pragma unroll
    for (int i = 0; i < 2; i++)
#pragma unroll
        for (int j = 0; j < 6; j++) acc[i][j] = 0.f;

    const int ulr = tid >> 3, ulc = (tid & 7) << 2;
    const int kend = ks * 512 + 512;
    for (int k0 = ks * 512; k0 < kend; k0 += 32) {
        float4 uv = *(const float4*)(g_u + (size_t)(m0 + ulr) * DINNER + k0 + ulc);
        Us[ulr][ulc + 0] = uv.x; Us[ulr][ulc + 1] = uv.y;
        Us[ulr][ulc + 2] = uv.z; Us[ulr][ulc + 3] = uv.w;
#pragma unroll
        for (int i = 0; i < 3; i++) {
            int idx = tid + i * 256;
            int wr = idx >> 3, wc = (idx & 7) << 2;
            float4 wv = *(const float4*)(W + (size_t)wr * DINNER + k0 + wc);
            Ws[wr][wc + 0] = wv.x; Ws[wr][wc + 1] = wv.y;
            Ws[wr][wc + 2] = wv.z; Ws[wr][wc + 3] = wv.w;
        }
        __syncthreads();
#pragma unroll 8
        for (int k = 0; k < 32; k++) {
            float u0 = Us[tm * 2 + 0][k];
            float u1 = Us[tm * 2 + 1][k];
#pragma unroll
            for (int j = 0; j < 6; j++) {
                float w = Ws[tn * 6 + j][k];
                acc[0][j] = fmaf(u0, w, acc[0][j]);
                acc[1][j] = fmaf(u1, w, acc[1][j]);
            }
        }
        __syncthreads();
    }
    float* dst = g_xpart + (size_t)ks * MTOT * NXPROJ;
#pragma unroll
    for (int i = 0; i < 2; i++)
#pragma unroll
        for (int j = 0; j < 6; j++)
            dst[(size_t)(m0 + tm * 2 + i) * NXPROJ + tn * 6 + j] = acc[i][j];
}

__global__ void xdbl_reduce_kernel()
{
    const int idx = blockIdx.x * blockDim.x + threadIdx.x;  // float4 idx < 49152
    const float4* p = (const float4*)g_xpart;
    const int S = MTOT * NXPROJ / 4;
    float4 a = p[idx], b = p[idx + S], c = p[idx + 2 * S], d = p[idx + 3 * S];
    ((float4*)g_xdbl)[idx] = make_float4(a.x + b.x + c.x + d.x, a.y + b.y + c.y + d.y,
                                         a.z + b.z + c.z + d.z, a.w + b.w + c.w + d.w);
}

// ---------------- delta (transposed): softplus(dt_low @ dt_w^T + 2*dt_b) ----------------
__global__ void dt_delta_kernel(const float* __restrict__ Wd, const float* __restrict__ bd)
{
    __shared__ float XsT[64][68];
    __shared__ float WsT[64][68];
    const int tid = threadIdx.x;                     // 256
    const int m0 = blockIdx.x * 64, d0 = blockIdx.y * 64;
    const int r = tid & 63, cb = tid >> 6;           // cb 0..3
#pragma unroll
    for (int q = 0; q < 4; q++) {
        const int c = cb * 16 + q * 4;
        float4 xv = *(const float4*)(g_xdbl + (size_t)(m0 + r) * NXPROJ + c);
        XsT[c + 0][r] = xv.x; XsT[c + 1][r] = xv.y;
        XsT[c + 2][r] = xv.z; XsT[c + 3][r] = xv.w;
        float4 wv = *(const float4*)(Wd + (size_t)(d0 + r) * DTRANK + c);
        WsT[c + 0][r] = wv.x; WsT[c + 1][r] = wv.y;
        WsT[c + 2][r] = wv.z; WsT[c + 3][r] = wv.w;
    }
    __syncthreads();
    const int tx = tid & 15, ty = tid >> 4;
    float acc[4][4];
#pragma unroll
    for (int i = 0; i < 4; i++)
#pragma unroll
        for (int j = 0; j < 4; j++) acc[i][j] = 0.f;
#pragma unroll 8
    for (int k = 0; k < 64; k++) {
        float4 xv = *(const float4*)&XsT[k][ty * 4];
        float4 wv = *(const float4*)&WsT[k][tx * 4];
        float xa[4] = {xv.x, xv.y, xv.z, xv.w};
        float wa[4] = {wv.x, wv.y, wv.z, wv.w};
#pragma unroll
        for (int i = 0; i < 4; i++)
#pragma unroll
            for (int j = 0; j < 4; j++)
                acc[i][j] = fmaf(xa[i], wa[j], acc[i][j]);
    }
    const int b = m0 >> 10;
    const int lb = (m0 & 1023) + ty * 4;
#pragma unroll
    for (int j = 0; j < 4; j++) {
        const int d = d0 + tx * 4 + j;
        const float b2 = 2.f * bd[d];
        float* drow = g_dT + (size_t)(b * DINNER + d) * SEQLEN;
#pragma unroll
        for (int i = 0; i < 4; i++) {
            float x = acc[i][j] + b2;
            float sp = (x > 20.f) ? x : log1pf(__expf(x));
            drow[lb + i] = sp;
        }
    }
}

// ---------------- selective scan: lane-per-state, 2 channels per warp ----------------
__global__ void scan_kernel(const float* __restrict__ A_log)
{
    const int warp = (blockIdx.x * blockDim.x + threadIdx.x) >> 5;
    const int lane = threadIdx.x & 31;
    const int b = warp >> 10;
    const int dp = warp & 1023;
    const int half = lane >> 4, n = lane & 15;
    const int d = dp * 2 + half;
    const int ch = b * DINNER + d;
    const float a = -__expf(A_log[d * DSTATE + n]);
    const float* dch = g_dT + (size_t)ch * SEQLEN;
    const float* uch = g_uT + (size_t)ch * SEQLEN;
    const int mbase = b * SEQLEN;
    float s = 0.f;
#pragma unroll 4
    for (int l = 0; l < SEQLEN; l++) {
        const int m = mbase + l;
        const float dl = dch[l];
        const float uu = uch[l];
        const float Bn = g_xdbl[(size_t)m * NXPROJ + DTRANK + n];
        const float Cn = g_xdbl[(size_t)m * NXPROJ + DTRANK + DSTATE + n];
        s = fmaf(__expf(dl * a), s, dl * uu * Bn);
        float c = s * Cn;
        c += __shfl_xor_sync(0xffffffffu, c, 8);
        c += __shfl_xor_sync(0xffffffffu, c, 4);
        c += __shfl_xor_sync(0xffffffffu, c, 2);
        c += __shfl_xor_sync(0xffffffffu, c, 1);
        if (n == 0) g_y[(size_t)m * DINNER + d] = c;
    }
}

// ---------------- gating fused with bf16 split ----------------
__global__ void gate_split_kernel(const float* __restrict__ Dv)
{
    const int i4 = blockIdx.x * blockDim.x + threadIdx.x;   // float4 idx
    const int m = (i4 * 4) >> 11, d = (i4 * 4) & 2047;
    float4 y = ((const float4*)g_y)[i4];
    float4 u = ((const float4*)g_u)[i4];
    float4 z = *(const float4*)(g_xz + (size_t)m * (2 * DINNER) + DINNER + d);
    float4 dv = *(const float4*)(Dv + d);
    float v[4];
    v[0] = (y.x + u.x * dv.x) * siluf(z.x);
    v[1] = (y.y + u.y * dv.y) * siluf(z.y);
    v[2] = (y.z + u.z * dv.z) * siluf(z.z);
    v[3] = (y.w + u.w * dv.w) * siluf(z.w);
    union { __nv_bfloat16 h[4]; uint2 u2; } H, L;
#pragma unroll
    for (int i = 0; i < 4; i++) {
        __nv_bfloat16 hh = __float2bfloat16(v[i]);
        H.h[i] = hh;
        L.h[i] = __float2bfloat16(v[i] - __bfloat162float(hh));
    }
    ((uint2*)g_y2H)[i4] = H.u2;
    ((uint2*)g_y2L)[i4] = L.u2;
}

// ---------------- launcher ----------------
extern "C" void kernel_launch(void* const* d_in, const int* in_sizes, int n_in,
                              void* d_out, int out_size)
{
    const float* hs      = (const float*)d_in[0];  // [2,1024,1024]
    const float* inW     = (const float*)d_in[1];  // [4096,1024]
    const float* convW   = (const float*)d_in[2];  // [2048,1,4]
    const float* convB   = (const float*)d_in[3];  // [2048]
    const float* xprojW  = (const float*)d_in[4];  // [96,2048]
    const float* dtW     = (const float*)d_in[5];  // [2048,64]
    const float* dtB     = (const float*)d_in[6];  // [2048]
    const float* A_log   = (const float*)d_in[7];  // [2048,16]
    const float* Dv      = (const float*)d_in[8];  // [2048]
    const float* outW    = (const float*)d_in[9];  // [1024,2048]
    float* out = (float*)d_out;

    float* p_xz;
    __nv_bfloat16 *p_hsH, *p_hsL, *p_inWH, *p_inWL, *p_y2H, *p_y2L, *p_outWH, *p_outWL;
    cudaGetSymbolAddress((void**)&p_xz,    g_xz);
    cudaGetSymbolAddress((void**)&p_hsH,   g_hsH);
    cudaGetSymbolAddress((void**)&p_hsL,   g_hsL);
    cudaGetSymbolAddress((void**)&p_inWH,  g_inWH);
    cudaGetSymbolAddress((void**)&p_inWL,  g_inWL);
    cudaGetSymbolAddress((void**)&p_y2H,   g_y2H);
    cudaGetSymbolAddress((void**)&p_y2L,   g_y2L);
    cudaGetSymbolAddress((void**)&p_outWH, g_outWH);
    cudaGetSymbolAddress((void**)&p_outWL, g_outWL);

    static bool attr_set = false;
    if (!attr_set) {
        cudaFuncSetAttribute(mma_gemm<128>, cudaFuncAttributeMaxDynamicSharedMemorySize, GEMM1_SMEM);
        cudaFuncSetAttribute(mma_gemm<64>,  cudaFuncAttributeMaxDynamicSharedMemorySize, GEMM4_SMEM);
        attr_set = true;
    }

    // 0) split inputs to hi/lo bf16
    split_kernel<<<(MTOT * DMODEL / 4) / 256, 256>>>(hs, p_hsH, p_hsL);
    split_kernel<<<(2 * DINNER * DMODEL / 4) / 256, 256>>>(inW, p_inWH, p_inWL);
    split_kernel<<<(DMODEL * DINNER / 4) / 256, 256>>>(outW, p_outWH, p_outWL);

    // 1) xz = hs @ in_proj_w^T (tensor cores, BN=128)
    mma_gemm<128><<<dim3(2 * DINNER / 128, MTOT / 128), 256, GEMM1_SMEM>>>(
        p_hsH, p_hsL, p_inWH, p_inWL, p_xz, 2 * DINNER, DMODEL);

    // 2) causal depthwise conv + SiLU -> u, uT
    conv_silu_kernel<<<dim3(MTOT / 32, DINNER / 32), 256>>>(convW, convB);

    // 3) x_dbl = u @ x_proj_w^T (split-K=4 + reduce)
    gemm_xdbl_kernel<<<dim3(MTOT / 32, 4), 256>>>(xprojW);
    xdbl_reduce_kernel<<<(MTOT * NXPROJ / 4) / 256, 256>>>();

    // 4) delta (transposed layout)
    dt_delta_kernel<<<dim3(MTOT / 64, DINNER / 64), 256>>>(dtW, dtB);

    // 5) selective scan
    scan_kernel<<<(BATCH * DINNER / 2) / 8, 256>>>(A_log);   // 2048 warps

    // 6) gating + bf16 split (fused)
    gate_split_kernel<<<(MTOT * DINNER / 4) / 256, 256>>>(Dv);

    // 7) out = y2 @ out_proj_w^T (tensor cores, BN=64 -> 256 CTAs)
    mma_gemm<64><<<dim3(DMODEL / 64, MTOT / 128), 256, GEMM4_SMEM>>>(
        p_y2H, p_y2L, p_outWH, p_outWL, out, DMODEL, DINNER);
}